// round 3
// baseline (speedup 1.0000x reference)
#include <cuda_runtime.h>
#include <cstdint>

// Problem constants
#define BB   8
#define LL   200
#define DD   128
#define HH   4
#define HS   32
#define HB   (HH*BB)        // 32
#define NROW (HB*LL)        // 6400
#define CAP  204

// Scratch (device globals; no allocation allowed)
__device__ float g_a [HB*LL*HS];
__device__ float g_b [HB*LL*HS];
__device__ float g_sv[HB*LL*HS];
__device__ float g_raw[NROW*LL];       // 5.12 MB; only j<=i valid
__device__ int   g_top[NROW*3];
__device__ int   g_cnt[NROW];
__device__ int   g_list[NROW*CAP];

// ---------------------------------------------------------------------------
// Stage 1: a = seqs@W1^T+b1, b = seqs@W2^T+b2, sv = seqs@W3^T+b3
// Output layout: [bh][L][HS], bh = h*B + b.
// ---------------------------------------------------------------------------
__global__ void k_gemm(const float* __restrict__ seqs,
                       const float* __restrict__ w1, const float* __restrict__ b1,
                       const float* __restrict__ w2, const float* __restrict__ b2,
                       const float* __restrict__ w3, const float* __restrict__ b3)
{
    __shared__ float st[32][DD];
    const int m   = blockIdx.y;
    const float* w    = (m == 0) ? w1 : (m == 1) ? w2 : w3;
    const float* bias = (m == 0) ? b1 : (m == 1) ? b2 : b3;
    float* dst        = (m == 0) ? g_a : (m == 1) ? g_b : g_sv;

    const int row0 = blockIdx.x * 32;
    const int tid  = threadIdx.x;

    for (int idx = tid; idx < 32 * DD; idx += 128)
        st[idx >> 7][idx & 127] = seqs[(row0 + (idx >> 7)) * DD + (idx & 127)];
    __syncthreads();

    float acc[32];
#pragma unroll
    for (int r = 0; r < 32; r++) acc[r] = 0.f;

    const int o = tid;
    const float4* w4 = (const float4*)(w + o * DD);
    for (int k4 = 0; k4 < DD / 4; k4++) {
        float4 wv = w4[k4];
#pragma unroll
        for (int r = 0; r < 32; r++) {
            float4 sv = *(const float4*)&st[r][k4 * 4];
            acc[r] += sv.x * wv.x + sv.y * wv.y + sv.z * wv.z + sv.w * wv.w;
        }
    }

    const float bb = bias[o];
    const int h = o >> 5, hs = o & 31;
#pragma unroll
    for (int r = 0; r < 32; r++) {
        int n = row0 + r;
        int b_ = n / LL, i = n % LL;
        int bh = h * BB + b_;
        dst[(bh * LL + i) * HS + hs] = acc[r] + bb;
    }
}

// ---------------------------------------------------------------------------
// Stage 2 (fused raw + top-k):
// Block per (b,i), 128 threads. Tile s = b + ti (32 j x 128 ch) in smem.
// Thread (h,lane) computes raw[bh][i][j] for j = jt+lane via a 32-len dot.
// Per-thread local top-3, then per-head smem merge with exact lax.top_k
// tie-breaking (value desc, index asc), incl. synthetic zero candidates
// for the masked upper region (j = i+1..i+3).
// ---------------------------------------------------------------------------
__global__ void k_rawtop(const float* __restrict__ tm)
{
    const int i = blockIdx.x, b = blockIdx.y;
    const int tid = threadIdx.x;
    const int h = tid >> 5, lane = tid & 31;
    const int bh = h * BB + b;
    const int rg = bh * LL + i;

    __shared__ float ss[32][129];      // s tile, pad-129: conflict-free
    __shared__ float sa[DD];           // a row (all heads)
    __shared__ float tv[3][128];       // per-lane top3 values
    __shared__ int   tj[3][128];       // per-lane top3 indices

    // load a row: d = h*32+hs channel of (b,i)
    {
        int d = tid, hh = d >> 5, hs = d & 31;
        sa[d] = g_a[((hh * BB + b) * LL + i) * HS + hs];
    }
    __syncthreads();

    // a in registers + |a| per head (warp reduce, once)
    float areg[HS];
#pragma unroll
    for (int k = 0; k < HS; k++) areg[k] = sa[h * HS + k];
    float an = areg[lane] * areg[lane]; // each lane squares its own channel
    {
        float t = sa[h * HS + lane];
        an = t * t;
#pragma unroll
        for (int s = 16; s; s >>= 1) an += __shfl_xor_sync(0xffffffffu, an, s);
        an = sqrtf(an);
    }

    // local top-3 (v desc, j asc via strict > and ascending j visit order)
    float v0 = -3.4e38f, v1 = -3.4e38f, v2 = -3.4e38f;
    int   j0 = -1, j1 = -1, j2 = -1;

    const size_t tmbase = ((size_t)(b * LL + i) * LL) * DD;
    float* rrow = g_raw + rg * LL;

    for (int jt = 0; jt <= i; jt += 32) {
        const int jmax = min(32, i + 1 - jt);
        // cooperative tile load: s[jj][d] = tm[b,i,jt+jj,d] + b[bh(d),jt+jj,hs(d)]
        for (int jj = 0; jj < jmax; jj++) {
            int d = tid, hh = d >> 5, hs = d & 31;
            int j = jt + jj;
            float tiv = tm[tmbase + (size_t)j * DD + d];
            float bv  = g_b[((hh * BB + b) * LL + j) * HS + hs];
            ss[jj][d] = tiv + bv;
        }
        __syncthreads();

        if (lane < jmax) {
            int j = jt + lane;
            float num = 0.f, den = 0.f;
#pragma unroll
            for (int k = 0; k < HS; k++) {
                float sv = ss[lane][h * HS + k];
                num += areg[k] * sv;
                den += sv * sv;
            }
            float v = num / (an * sqrtf(den) + 1e-6f);
            rrow[j] = v;
            if (v > v0)      { v2=v1; j2=j1; v1=v0; j1=j0; v0=v; j0=j; }
            else if (v > v1) { v2=v1; j2=j1; v1=v;  j1=j; }
            else if (v > v2) { v2=v;  j2=j; }
        }
        __syncthreads();
    }

    tv[0][tid]=v0; tj[0][tid]=j0;
    tv[1][tid]=v1; tj[1][tid]=j1;
    tv[2][tid]=v2; tj[2][tid]=j2;
    __syncthreads();

    // per-head merge (thread h of first warp handles head h)
    if (tid < HH) {
        const int hh = tid;
        float V0=-3.4e38f, V1=-3.4e38f, V2=-3.4e38f;
        int   I0=0x7fffffff, I1=0x7fffffff, I2=0x7fffffff;
        auto ins = [&](float v, int j) {
            if (j < 0) return;
            if (v > V0 || (v == V0 && j < I0)) { V2=V1;I2=I1; V1=V0;I1=I0; V0=v;I0=j; }
            else if (v > V1 || (v == V1 && j < I1)) { V2=V1;I2=I1; V1=v;I1=j; }
            else if (v > V2 || (v == V2 && j < I2)) { V2=v;I2=j; }
        };
        for (int l = 0; l < 32; l++) {
            int t = hh * 32 + l;
            ins(tv[0][t], tj[0][t]);
            ins(tv[1][t], tj[1][t]);
            ins(tv[2][t], tj[2][t]);
        }
        // masked upper region contributes exact zeros at j = i+1.. (index-asc ties)
#pragma unroll
        for (int q = 1; q <= 3; q++) {
            int jz = i + q;
            if (jz < LL) ins(0.0f, jz);
        }
        int rgo = (hh * BB + b) * LL + i;
        g_top[rgo * 3 + 0] = I0;
        g_top[rgo * 3 + 1] = I1;
        g_top[rgo * 3 + 2] = I2;
        g_cnt[rgo] = 0;
    }
}

// ---------------------------------------------------------------------------
// Stage 3: symmetrized-mask candidate lists (lower-triangle only).
// ---------------------------------------------------------------------------
__global__ void k_lists()
{
    const int rg = blockIdx.x * 256 + threadIdx.x;
    if (rg >= NROW) return;
    const int bh = rg / LL, r = rg % LL;
#pragma unroll
    for (int q = 0; q < 3; q++) {
        int t = g_top[rg * 3 + q];
        if (t <= r) {
            int p = atomicAdd(&g_cnt[rg], 1);
            if (p < CAP) g_list[rg * CAP + p] = t;
        } else {
            int tg = bh * LL + t;
            int p = atomicAdd(&g_cnt[tg], 1);
            if (p < CAP) g_list[tg * CAP + p] = r;
        }
    }
}

// ---------------------------------------------------------------------------
// Stage 4 (fused sparse gather + LayerNorm):
// Block per (b,i), 128 threads (warp = head, lane = hs channel).
//   out[bh,i,:] = sum_j sg[i,j]*sv[bh,j,:],  tio = sum_j sg[i,j]*ti[b,i,j,:]
// Dedup via 200-bit bitmask, ascending-j iteration (deterministic).
// Then block LayerNorm over D=128 on 'out'.
// ---------------------------------------------------------------------------
__global__ void k_gather_ln(const float* __restrict__ tm,
                            const float* __restrict__ gam,
                            const float* __restrict__ bet,
                            float* __restrict__ out_ln,
                            float* __restrict__ out_tio)
{
    const int i = blockIdx.x, b = blockIdx.y;
    const int tid = threadIdx.x;
    const int h = tid >> 5, lane = tid & 31;
    const int bh = h * BB + b;
    const int rg = bh * LL + i;

    __shared__ unsigned bm[HH][7];
    __shared__ float red[4];

    if (lane < 7) bm[h][lane] = 0u;
    __syncwarp();

    const int n = min(g_cnt[rg], CAP);
    for (int c = lane; c < n; c += 32) {
        int j = g_list[rg * CAP + c];
        atomicOr(&bm[h][j >> 5], 1u << (j & 31));
    }
    __syncwarp();

    float ao = 0.f, at = 0.f;
    const float* rrow = g_raw + rg * LL;
    const float* tmb  = tm + (size_t)(b * LL + i) * LL * DD + h * HS + lane;
    const float* svb  = g_sv + bh * LL * HS + lane;

    for (int w = 0; w < 7; w++) {
        unsigned m = bm[h][w];
        while (m) {
            int bit = __ffs(m) - 1;
            m &= m - 1;
            int j = w * 32 + bit;
            float sgv = rrow[j];
            ao += sgv * svb[j * HS];
            at += sgv * tmb[(size_t)j * DD];
        }
    }

    const int d = tid;                 // d = h*HS + lane
    out_tio[(b * LL + i) * DD + d] = at;

    // ---- LayerNorm over the 128 'ao' values ----
    float s = ao;
#pragma unroll
    for (int k = 16; k; k >>= 1) s += __shfl_xor_sync(0xffffffffu, s, k);
    if (lane == 0) red[h] = s;
    __syncthreads();
    float mu = (red[0] + red[1] + red[2] + red[3]) * (1.f / 128.f);
    __syncthreads();

    float dv = ao - mu;
    float s2 = dv * dv;
#pragma unroll
    for (int k = 16; k; k >>= 1) s2 += __shfl_xor_sync(0xffffffffu, s2, k);
    if (lane == 0) red[h] = s2;
    __syncthreads();
    float var = (red[0] + red[1] + red[2] + red[3]) * (1.f / 128.f);

    out_ln[(b * LL + i) * DD + d] = dv / sqrtf(var + 1e-8f) * gam[d] + bet[d];
}

// ---------------------------------------------------------------------------
extern "C" void kernel_launch(void* const* d_in, const int* in_sizes, int n_in,
                              void* d_out, int out_size)
{
    const float* seqs = (const float*)d_in[0];
    // d_in[1] = attention_mask (known causal triu) — unused
    const float* tm   = (const float*)d_in[2];
    const float* w1   = (const float*)d_in[3];
    const float* b1   = (const float*)d_in[4];
    const float* w2   = (const float*)d_in[5];
    const float* b2   = (const float*)d_in[6];
    const float* w3   = (const float*)d_in[7];
    const float* b3   = (const float*)d_in[8];
    const float* lng  = (const float*)d_in[9];
    const float* lnb  = (const float*)d_in[10];

    float* out_ln  = (float*)d_out;
    float* out_tio = out_ln + BB * LL * DD;

    k_gemm     <<<dim3(50, 3),  128>>>(seqs, w1, b1, w2, b2, w3, b3);
    k_rawtop   <<<dim3(LL, BB), 128>>>(tm);
    k_lists    <<<(NROW + 255) / 256, 256>>>();
    k_gather_ln<<<dim3(LL, BB), 128>>>(tm, lng, lnb, out_ln, out_tio);
}

// round 4
// speedup vs baseline: 1.6339x; 1.6339x over previous
#include <cuda_runtime.h>
#include <cstdint>

// Problem constants
#define BB   8
#define LL   200
#define DD   128
#define HH   4
#define HS   32
#define HB   (HH*BB)        // 32
#define NROW (HB*LL)        // 6400
#define CAP  204            // max per-row candidates: own(<=3) + incoming(<=199)

// Scratch (device globals; no allocation allowed)
__device__ float g_ad[BB*LL*DD];       // a in [b][i][d] layout (d = h*32+hs)
__device__ float g_bd[BB*LL*DD];       // b in [b][j][d] layout
__device__ float g_sv[HB*LL*HS];       // sv in [bh][j][hs] layout
__device__ float g_raw[NROW*LL];       // only j<=i valid
__device__ int   g_cnt[NROW];
__device__ int   g_list[NROW*CAP];

// ---------------------------------------------------------------------------
// Stage 1: three projections. a,b stored [B][L][D]; sv stored per-head.
// m==0 branch also zeroes g_cnt (exactly NROW threads across its 50 blocks).
// ---------------------------------------------------------------------------
__global__ void k_gemm(const float* __restrict__ seqs,
                       const float* __restrict__ w1, const float* __restrict__ b1,
                       const float* __restrict__ w2, const float* __restrict__ b2,
                       const float* __restrict__ w3, const float* __restrict__ b3)
{
    __shared__ float st[32][DD];
    const int m   = blockIdx.y;
    const float* w    = (m == 0) ? w1 : (m == 1) ? w2 : w3;
    const float* bias = (m == 0) ? b1 : (m == 1) ? b2 : b3;

    const int row0 = blockIdx.x * 32;
    const int tid  = threadIdx.x;

    if (m == 0) g_cnt[blockIdx.x * 128 + tid] = 0;

    for (int idx = tid; idx < 32 * DD; idx += 128)
        st[idx >> 7][idx & 127] = seqs[(row0 + (idx >> 7)) * DD + (idx & 127)];
    __syncthreads();

    float acc[32];
#pragma unroll
    for (int r = 0; r < 32; r++) acc[r] = 0.f;

    const int o = tid;
    const float4* w4 = (const float4*)(w + o * DD);
    for (int k4 = 0; k4 < DD / 4; k4++) {
        float4 wv = w4[k4];
#pragma unroll
        for (int r = 0; r < 32; r++) {
            float4 sv = *(const float4*)&st[r][k4 * 4];
            acc[r] += sv.x * wv.x + sv.y * wv.y + sv.z * wv.z + sv.w * wv.w;
        }
    }

    const float bb = bias[o];
    if (m == 2) {
        const int h = o >> 5, hs = o & 31;
#pragma unroll
        for (int r = 0; r < 32; r++) {
            int n = row0 + r;
            int b_ = n / LL, i = n % LL;
            g_sv[((h * BB + b_) * LL + i) * HS + hs] = acc[r] + bb;
        }
    } else {
        float* dst = (m == 0) ? g_ad : g_bd;
#pragma unroll
        for (int r = 0; r < 32; r++)
            dst[(row0 + r) * DD + o] = acc[r] + bb;
    }
}

// ---------------------------------------------------------------------------
// Stage 2 (fused raw + top-k + list push):
// Block per (b,i), 4 warps. Warp w handles j ≡ w (mod 4), unrolled x2.
// Lane ℓ: head h = ℓ>>3, channel quad q = ℓ&7 (4 channels via float4).
// One LDG.128/thread for ti and for b per j; num/den via 3x shfl_xor each.
// q==0 lanes track per-warp top-3 per head; smem merge (exact lax.top_k
// tie-break: value desc, index asc) incl. zero candidates for masked j>i;
// then push symmetrized-mask candidate lists via atomics.
// ---------------------------------------------------------------------------
__global__ void k_rawtop(const float* __restrict__ tm)
{
    const int i = blockIdx.x, b = blockIdx.y;
    const int tid = threadIdx.x;
    const int w = tid >> 5, lane = tid & 31;
    const int h = lane >> 3;
    const int q = lane & 7;

    __shared__ float tvs[4][HH][3];
    __shared__ int   tjs[4][HH][3];

    const float4 a4 = *(const float4*)&g_ad[(size_t)(b * LL + i) * DD + lane * 4];
    float an2 = a4.x * a4.x + a4.y * a4.y + a4.z * a4.z + a4.w * a4.w;
    an2 += __shfl_xor_sync(0xffffffffu, an2, 4);
    an2 += __shfl_xor_sync(0xffffffffu, an2, 2);
    an2 += __shfl_xor_sync(0xffffffffu, an2, 1);
    const float an = sqrtf(an2);

    float v0 = -3.4e38f, v1 = -3.4e38f, v2 = -3.4e38f;
    int   j0 = -1, j1 = -1, j2 = -1;

    const float* tmp = tm   + (size_t)(b * LL + i) * LL * DD + lane * 4;
    const float* bp  = g_bd + (size_t)b * LL * DD + lane * 4;
    float* rrow = g_raw + (size_t)((h * BB + b) * LL + i) * LL;

    for (int j = w; j <= i; j += 8) {
        const int  jB = j + 4;
        const bool pB = (jB <= i);

        float4 tA = *(const float4*)(tmp + (size_t)j * DD);
        float4 bA = *(const float4*)(bp  + (size_t)j * DD);
        float4 tB, bv;
        if (pB) {
            tB = *(const float4*)(tmp + (size_t)jB * DD);
            bv = *(const float4*)(bp  + (size_t)jB * DD);
        }

        {
            float sx = tA.x + bA.x, sy = tA.y + bA.y, sz = tA.z + bA.z, sw = tA.w + bA.w;
            float num = a4.x * sx + a4.y * sy + a4.z * sz + a4.w * sw;
            float den = sx * sx + sy * sy + sz * sz + sw * sw;
            num += __shfl_xor_sync(0xffffffffu, num, 4);
            den += __shfl_xor_sync(0xffffffffu, den, 4);
            num += __shfl_xor_sync(0xffffffffu, num, 2);
            den += __shfl_xor_sync(0xffffffffu, den, 2);
            num += __shfl_xor_sync(0xffffffffu, num, 1);
            den += __shfl_xor_sync(0xffffffffu, den, 1);
            if (q == 0) {
                float v = num / (an * sqrtf(den) + 1e-6f);
                rrow[j] = v;
                if (v > v0)      { v2 = v1; j2 = j1; v1 = v0; j1 = j0; v0 = v; j0 = j; }
                else if (v > v1) { v2 = v1; j2 = j1; v1 = v;  j1 = j; }
                else if (v > v2) { v2 = v;  j2 = j; }
            }
        }
        if (pB) {
            float sx = tB.x + bv.x, sy = tB.y + bv.y, sz = tB.z + bv.z, sw = tB.w + bv.w;
            float num = a4.x * sx + a4.y * sy + a4.z * sz + a4.w * sw;
            float den = sx * sx + sy * sy + sz * sz + sw * sw;
            num += __shfl_xor_sync(0xffffffffu, num, 4);
            den += __shfl_xor_sync(0xffffffffu, den, 4);
            num += __shfl_xor_sync(0xffffffffu, num, 2);
            den += __shfl_xor_sync(0xffffffffu, den, 2);
            num += __shfl_xor_sync(0xffffffffu, num, 1);
            den += __shfl_xor_sync(0xffffffffu, den, 1);
            if (q == 0) {
                float v = num / (an * sqrtf(den) + 1e-6f);
                rrow[jB] = v;
                if (v > v0)      { v2 = v1; j2 = j1; v1 = v0; j1 = j0; v0 = v; j0 = jB; }
                else if (v > v1) { v2 = v1; j2 = j1; v1 = v;  j1 = jB; }
                else if (v > v2) { v2 = v;  j2 = jB; }
            }
        }
    }

    if (q == 0) {
        tvs[w][h][0] = v0; tjs[w][h][0] = j0;
        tvs[w][h][1] = v1; tjs[w][h][1] = j1;
        tvs[w][h][2] = v2; tjs[w][h][2] = j2;
    }
    __syncthreads();

    // per-head merge + list push (thread hh handles head hh)
    if (tid < HH) {
        const int hh = tid;
        float V0 = -3.4e38f, V1 = -3.4e38f, V2 = -3.4e38f;
        int   I0 = 0x7fffffff, I1 = 0x7fffffff, I2 = 0x7fffffff;
        auto ins = [&](float v, int j) {
            if (j < 0) return;
            if (v > V0 || (v == V0 && j < I0)) { V2 = V1; I2 = I1; V1 = V0; I1 = I0; V0 = v; I0 = j; }
            else if (v > V1 || (v == V1 && j < I1)) { V2 = V1; I2 = I1; V1 = v; I1 = j; }
            else if (v > V2 || (v == V2 && j < I2)) { V2 = v; I2 = j; }
        };
#pragma unroll
        for (int ww = 0; ww < 4; ww++)
#pragma unroll
            for (int qq = 0; qq < 3; qq++)
                ins(tvs[ww][hh][qq], tjs[ww][hh][qq]);
#pragma unroll
        for (int z = 1; z <= 3; z++) {
            int jz = i + z;
            if (jz < LL) ins(0.0f, jz);   // masked zeros (index-asc ties)
        }
        const int bh = hh * BB + b;
        const int rg = bh * LL + i;
        int sel[3] = {I0, I1, I2};
#pragma unroll
        for (int s = 0; s < 3; s++) {
            int t = sel[s];
            if (t <= i) {
                int p = atomicAdd(&g_cnt[rg], 1);
                if (p < CAP) g_list[rg * CAP + p] = t;
            } else {
                int tg = bh * LL + t;
                int p = atomicAdd(&g_cnt[tg], 1);
                if (p < CAP) g_list[tg * CAP + p] = i;
            }
        }
    }
}

// ---------------------------------------------------------------------------
// Stage 3 (fused sparse gather + LayerNorm): block per (b,i), warp = head.
// Dedup candidates via 200-bit bitmask; ascending-j iteration (deterministic).
// ---------------------------------------------------------------------------
__global__ void k_gather_ln(const float* __restrict__ tm,
                            const float* __restrict__ gam,
                            const float* __restrict__ bet,
                            float* __restrict__ out_ln,
                            float* __restrict__ out_tio)
{
    const int i = blockIdx.x, b = blockIdx.y;
    const int tid = threadIdx.x;
    const int h = tid >> 5, lane = tid & 31;
    const int bh = h * BB + b;
    const int rg = bh * LL + i;

    __shared__ unsigned bm[HH][7];
    __shared__ float red[4];

    if (lane < 7) bm[h][lane] = 0u;
    __syncwarp();

    const int n = min(g_cnt[rg], CAP);
    for (int c = lane; c < n; c += 32) {
        int j = g_list[rg * CAP + c];
        atomicOr(&bm[h][j >> 5], 1u << (j & 31));
    }
    __syncwarp();

    float ao = 0.f, at = 0.f;
    const float* rrow = g_raw + (size_t)rg * LL;
    const float* tmb  = tm + (size_t)(b * LL + i) * LL * DD + h * HS + lane;
    const float* svb  = g_sv + (size_t)bh * LL * HS + lane;

    for (int w = 0; w < 7; w++) {
        unsigned m = bm[h][w];
        while (m) {
            int bit = __ffs(m) - 1;
            m &= m - 1;
            int j = w * 32 + bit;
            float sgv = rrow[j];
            ao += sgv * svb[j * HS];
            at += sgv * tmb[(size_t)j * DD];
        }
    }

    const int d = tid;                 // d = h*HS + lane
    out_tio[(b * LL + i) * DD + d] = at;

    // LayerNorm over the 128 'ao' values
    float s = ao;
#pragma unroll
    for (int k = 16; k; k >>= 1) s += __shfl_xor_sync(0xffffffffu, s, k);
    if (lane == 0) red[h] = s;
    __syncthreads();
    float mu = (red[0] + red[1] + red[2] + red[3]) * (1.f / 128.f);
    __syncthreads();

    float dv = ao - mu;
    float s2 = dv * dv;
#pragma unroll
    for (int k = 16; k; k >>= 1) s2 += __shfl_xor_sync(0xffffffffu, s2, k);
    if (lane == 0) red[h] = s2;
    __syncthreads();
    float var = (red[0] + red[1] + red[2] + red[3]) * (1.f / 128.f);

    out_ln[(b * LL + i) * DD + d] = dv / sqrtf(var + 1e-8f) * gam[d] + bet[d];
}

// ---------------------------------------------------------------------------
extern "C" void kernel_launch(void* const* d_in, const int* in_sizes, int n_in,
                              void* d_out, int out_size)
{
    const float* seqs = (const float*)d_in[0];
    // d_in[1] = attention_mask (known causal triu) — unused
    const float* tm   = (const float*)d_in[2];
    const float* w1   = (const float*)d_in[3];
    const float* b1   = (const float*)d_in[4];
    const float* w2   = (const float*)d_in[5];
    const float* b2   = (const float*)d_in[6];
    const float* w3   = (const float*)d_in[7];
    const float* b3   = (const float*)d_in[8];
    const float* lng  = (const float*)d_in[9];
    const float* lnb  = (const float*)d_in[10];

    float* out_ln  = (float*)d_out;
    float* out_tio = out_ln + BB * LL * DD;

    k_gemm     <<<dim3(50, 3),  128>>>(seqs, w1, b1, w2, b2, w3, b3);
    k_rawtop   <<<dim3(LL, BB), 128>>>(tm);
    k_gather_ln<<<dim3(LL, BB), 128>>>(tm, lng, lnb, out_ln, out_tio);
}